// round 15
// baseline (speedup 1.0000x reference)
#include <cuda_runtime.h>
#include <cuda_bf16.h>
#include <cstdint>

#define S_LEN 2048
#define D_DIM 512
#define NH 8
#define NROWS 4096   // B*S
#define NBH 16       // B*H

// ---------------- scratch (static device globals; no allocs) ----------------
__device__ float g_g[D_DIM];
__device__ float2 g_cu[NBH * S_LEN];                               // {cn, u}
__device__ __align__(128) __nv_bfloat16 g_Q1[NBH * S_LEN * 64];    // plane1 = bf16(Q)
__device__ __align__(128) __nv_bfloat16 g_Q2[NBH * S_LEN * 64];    // plane2 = bf16(hi+16*lo)
__device__ __align__(128) __nv_bfloat16 g_X1[NROWS * D_DIM];       // plane1 = bf16(x)
__device__ __align__(128) __nv_bfloat16 g_X2[NROWS * D_DIM];       // plane2 = bf16(xh+16xl)/4
__device__ __align__(128) __nv_bfloat16 g_W1[D_DIM * D_DIM];       // [n][k] bf16(0.9375*w)
__device__ __align__(128) __nv_bfloat16 g_W2[D_DIM * D_DIM];       // [n][k] plane2 (/4)
__device__ __align__(128) float g_Wt[D_DIM * D_DIM];               // [n][k] fp32
__device__ __align__(128) float g_pd[NBH * S_LEN * 16];            // den partials
__device__ __align__(128) float g_pn[NBH * S_LEN * 16];            // num partials

// ---------------- helpers ----------------
__device__ __forceinline__ float ex2(float x) {
    float r; asm("ex2.approx.ftz.f32 %0, %1;" : "=f"(r) : "f"(x)); return r;
}
__device__ __forceinline__ uint32_t smem_u32(const void* p) {
    uint32_t a;
    asm("{ .reg .u64 t; cvta.to.shared.u64 t, %1; cvt.u32.u64 %0, t; }" : "=r"(a) : "l"(p));
    return a;
}
#define LOG2E 1.4426950408889634f
#define SW128(o) ((o) ^ ((((uint32_t)(o)) >> 3) & 0x70))
#define SW64(o)  ((o) ^ ((((uint32_t)(o)) >> 3) & 0x30))

__device__ __forceinline__ void ldsm4(uint32_t* r, uint32_t addr) {
    asm volatile("ldmatrix.sync.aligned.m8n8.x4.shared.b16 {%0,%1,%2,%3}, [%4];"
                 : "=r"(r[0]), "=r"(r[1]), "=r"(r[2]), "=r"(r[3]) : "r"(addr));
}
__device__ __forceinline__ void mma16816(float* c, const uint32_t* a, const uint32_t* b) {
    asm volatile("mma.sync.aligned.m16n8k16.row.col.f32.bf16.bf16.f32 "
                 "{%0,%1,%2,%3}, {%4,%5,%6,%7}, {%8,%9}, {%0,%1,%2,%3};"
                 : "+f"(c[0]), "+f"(c[1]), "+f"(c[2]), "+f"(c[3])
                 : "r"(a[0]), "r"(a[1]), "r"(a[2]), "r"(a[3]), "r"(b[0]), "r"(b[1]));
}
__device__ __forceinline__ void cp16(uint32_t dst, const void* src) {
    asm volatile("cp.async.cg.shared.global [%0], [%1], 16;" :: "r"(dst), "l"(src));
}
__device__ __forceinline__ void cp_commit() {
    asm volatile("cp.async.commit_group;" ::: "memory");
}
template <int N>
__device__ __forceinline__ void cp_wait() {
    asm volatile("cp.async.wait_group %0;" :: "n"(N) : "memory");
}
// general-product two-plane split: plane1 = bf16(v), plane2 = bf16(h+16*l) * 0.25 (exact)
__device__ __forceinline__ uint32_t packgp(float a, float b, uint32_t& p2) {
    __nv_bfloat16 h0 = __float2bfloat16(a);
    __nv_bfloat16 h1 = __float2bfloat16(b);
    float f0 = __bfloat162float(h0), f1 = __bfloat162float(h1);
    __nv_bfloat162 hh; hh.x = h0; hh.y = h1;
    __nv_bfloat162 pp;
    pp.x = __float2bfloat16(fmaf(16.f, a - f0, f0) * 0.25f);
    pp.y = __float2bfloat16(fmaf(16.f, b - f1, f1) * 0.25f);
    p2 = *(uint32_t*)&pp;
    return *(uint32_t*)&hh;
}
// symmetric Gram two-plane split: plane1 = bf16(q), plane2 = bf16(h + 16*l)
__device__ __forceinline__ uint32_t packp(float a, float b, uint32_t& p2) {
    __nv_bfloat16 h0 = __float2bfloat16(a);
    __nv_bfloat16 h1 = __float2bfloat16(b);
    float f0 = __bfloat162float(h0), f1 = __bfloat162float(h1);
    __nv_bfloat162 hh; hh.x = h0; hh.y = h1;
    __nv_bfloat162 pp;
    pp.x = __float2bfloat16(fmaf(16.f, a - f0, f0));
    pp.y = __float2bfloat16(fmaf(16.f, b - f1, f1));
    p2 = *(uint32_t*)&pp;
    return *(uint32_t*)&hh;
}

// ---------------- convert_w: W[k][n] -> Wt / plane1(x15/16) / plane2 ------
__global__ __launch_bounds__(256) void convert_w(const float* __restrict__ W) {
    __shared__ float tile[32][33];
    int k0 = (blockIdx.x & 15) * 32;
    int n0 = (blockIdx.x >> 4) * 32;
    int tid = threadIdx.x;
    int r = tid >> 5, c = tid & 31;
#pragma unroll
    for (int p = 0; p < 4; p++)
        tile[p * 8 + r][c] = W[(size_t)(k0 + p * 8 + r) * 512 + n0 + c];
    __syncthreads();
#pragma unroll
    for (int p = 0; p < 4; p++) {
        int nr = p * 8 + r;
        float v = tile[c][nr];
        size_t o = (size_t)(n0 + nr) * 512 + k0 + c;
        g_Wt[o] = v;
        __nv_bfloat16 h = __float2bfloat16(v);
        float fh = __bfloat162float(h);
        g_W1[o] = __float2bfloat16(0.9375f * v);
        g_W2[o] = __float2bfloat16(fmaf(16.f, v - fh, fh) * 0.25f);
    }
}

// ---------------- calc_g ----------------
__global__ __launch_bounds__(256) void calc_g(const float* __restrict__ Wv) {
    int warp = blockIdx.x * 8 + (threadIdx.x >> 5);   // 512
    int lane = threadIdx.x & 31;
    const float* wt = g_Wt + (size_t)warp * 512;
    float a = 0.f;
#pragma unroll
    for (int m = 0; m < 16; m++) {
        int k = lane + 32 * m;
        a = fmaf(wt[k], Wv[k], a);
    }
#pragma unroll
    for (int o = 16; o > 0; o >>= 1) a += __shfl_xor_sync(0xffffffffu, a, o);
    if (lane == 0) g_g[warp] = a;
}

// ---------------- convert_x ----------------
__global__ __launch_bounds__(256) void convert_x(const float* __restrict__ X) {
    int gid = blockIdx.x * 256 + threadIdx.x;
    const float4* src = (const float4*)X;
    uint2* d1 = (uint2*)g_X1;
    uint2* d2 = (uint2*)g_X2;
#pragma unroll
    for (int r = 0; r < 2; r++) {
        int i = gid * 2 + r;
        float4 v = src[i];
        uint2 p1, p2;
        p1.x = packgp(v.x, v.y, p2.x);
        p1.y = packgp(v.z, v.w, p2.y);
        d1[i] = p1;
        d2[i] = p2;
    }
}

// ---------------- gemm_q: Q ≈ A1·W1 + A2·W2, single bank, K-chunk 32 ------
// stage: A1 8K | A2 8K | B1 4K | B2 4K = 24K; x2 = 48K. SW64 (64B rows).
#define GQ_STAGE 24576
#define GQ_A1 0
#define GQ_A2 8192
#define GQ_B1 16384
#define GQ_B2 20480
#define GQ_SMEM (2 * GQ_STAGE)

__device__ __forceinline__ void gq_load(uint32_t base,
        const __nv_bfloat16* A1, const __nv_bfloat16* A2,
        const __nv_bfloat16* B1, const __nv_bfloat16* B2,
        int kc, int tid) {
#pragma unroll
    for (int q = 0; q < 2; q++) {
        int idx = q * 256 + tid;           // 0..511 (128 rows x 4 groups)
        int row = idx >> 2, cg = idx & 3;
        uint32_t so = SW64((uint32_t)idx * 16);
        cp16(base + GQ_A1 + so, A1 + (size_t)row * 512 + kc + cg * 8);
        cp16(base + GQ_A2 + so, A2 + (size_t)row * 512 + kc + cg * 8);
    }
    {
        int idx = tid;                     // 0..255 (64 rows x 4 groups)
        int row = idx >> 2, cg = idx & 3;
        uint32_t so = SW64((uint32_t)idx * 16);
        cp16(base + GQ_B1 + so, B1 + (size_t)row * 512 + kc + cg * 8);
        cp16(base + GQ_B2 + so, B2 + (size_t)row * 512 + kc + cg * 8);
    }
}

__global__ __launch_bounds__(256, 3) void gemm_q() {
    extern __shared__ char sm[];
    uint32_t sb = smem_u32(sm);
    int tid = threadIdx.x, lane = tid & 31, w = tid >> 5;
    int bid = blockIdx.x;
    int r0 = (bid >> 3) * 128;
    int h = bid & 7;
    int b = r0 >> 11, srow0 = r0 & 2047;
    const __nv_bfloat16* A1 = g_X1 + (size_t)r0 * 512;
    const __nv_bfloat16* A2 = g_X2 + (size_t)r0 * 512;
    const __nv_bfloat16* B1 = g_W1 + (size_t)h * 64 * 512;
    const __nv_bfloat16* B2 = g_W2 + (size_t)h * 64 * 512;

    int row_a = w * 16 + (lane & 15);
    uint32_t sw64 = (uint32_t)((lane & 6) << 3);
    uint32_t a_hi16 = (uint32_t)((lane >> 4) * 16);
    int nrow_base = (lane & 7) + ((lane >> 4) << 3);
    uint32_t b_c16 = (uint32_t)(((lane >> 3) & 1) * 16);

    float cacc[8][4];
#pragma unroll
    for (int nb = 0; nb < 8; nb++)
#pragma unroll
        for (int r = 0; r < 4; r++) cacc[nb][r] = 0.f;

    gq_load(sb, A1, A2, B1, B2, 0, tid);
    cp_commit();

    for (int i = 0; i < 16; i++) {
        int buf = i & 1;
        __syncthreads();
        if (i < 15) {
            gq_load(sb + (buf ^ 1) * GQ_STAGE, A1, A2, B1, B2, (i + 1) * 32, tid);
            cp_commit();
            cp_wait<1>();
        } else {
            cp_wait<0>();
        }
        __syncthreads();
        uint32_t aB1 = sb + buf * GQ_STAGE + GQ_A1 + (uint32_t)row_a * 64;
        uint32_t aB2 = sb + buf * GQ_STAGE + GQ_A2 + (uint32_t)row_a * 64;
        uint32_t bB1 = sb + buf * GQ_STAGE + GQ_B1;
        uint32_t bB2 = sb + buf * GQ_STAGE + GQ_B2;
#pragma unroll
        for (int kk = 0; kk < 2; kk++) {
            uint32_t acol = ((uint32_t)(kk * 32) + a_hi16) ^ sw64;
            uint32_t a1[4], a2[4];
            ldsm4(a1, aB1 + acol);
            ldsm4(a2, aB2 + acol);
            uint32_t bcol = ((uint32_t)(kk * 32) + b_c16) ^ sw64;
#pragma unroll
            for (int nb2 = 0; nb2 < 4; nb2++) {
                uint32_t boff = (uint32_t)(nrow_base + nb2 * 16) * 64 + bcol;
                uint32_t b1[4], b2[4];
                ldsm4(b1, bB1 + boff);
                ldsm4(b2, bB2 + boff);
                mma16816(cacc[2 * nb2],     a1, b1);
                mma16816(cacc[2 * nb2 + 1], a1, b1 + 2);
                mma16816(cacc[2 * nb2],     a2, b2);
                mma16816(cacc[2 * nb2 + 1], a2, b2 + 2);
            }
        }
    }
    __syncthreads();

    // ---- norms + u = Q.g ----
    float sA = 0.f, sB = 0.f, uA = 0.f, uB = 0.f;
#pragma unroll
    for (int nb = 0; nb < 8; nb++) {
        int c0 = nb * 8 + (lane & 3) * 2;
        float2 gg = *(const float2*)&g_g[h * 64 + c0];
        sA = fmaf(cacc[nb][0], cacc[nb][0], sA);
        sA = fmaf(cacc[nb][1], cacc[nb][1], sA);
        sB = fmaf(cacc[nb][2], cacc[nb][2], sB);
        sB = fmaf(cacc[nb][3], cacc[nb][3], sB);
        uA = fmaf(cacc[nb][0], gg.x, uA);
        uA = fmaf(cacc[nb][1], gg.y, uA);
        uB = fmaf(cacc[nb][2], gg.x, uB);
        uB = fmaf(cacc[nb][3], gg.y, uB);
    }
#pragma unroll
    for (int o = 1; o <= 2; o <<= 1) {
        sA += __shfl_xor_sync(0xffffffffu, sA, o);
        sB += __shfl_xor_sync(0xffffffffu, sB, o);
        uA += __shfl_xor_sync(0xffffffffu, uA, o);
        uB += __shfl_xor_sync(0xffffffffu, uB, o);
    }
    int rA = w * 16 + (lane >> 2);
    if ((lane & 3) == 0) {
        int base = (b * 8 + h) * S_LEN + srow0;
        g_cu[base + rA]     = make_float2(-0.125f * LOG2E * sqrtf(sA), uA);
        g_cu[base + rA + 8] = make_float2(-0.125f * LOG2E * sqrtf(sB), uB);
    }

    // ---- stage Q planes (padded [128][33] u32) ----
    uint32_t* s1 = (uint32_t*)sm;
    uint32_t* s2 = (uint32_t*)(sm + 16896);
#pragma unroll
    for (int nb = 0; nb < 8; nb++) {
        int cslot = nb * 4 + (lane & 3);
        uint32_t p0, p1;
        uint32_t h0 = packp(cacc[nb][0], cacc[nb][1], p0);
        uint32_t h1 = packp(cacc[nb][2], cacc[nb][3], p1);
        s1[rA * 33 + cslot] = h0;
        s2[rA * 33 + cslot] = p0;
        s1[(rA + 8) * 33 + cslot] = h1;
        s2[(rA + 8) * 33 + cslot] = p1;
    }
    __syncthreads();
    uint32_t* d1 = (uint32_t*)(g_Q1 + ((size_t)(b * 8 + h) * S_LEN + srow0) * 64);
    uint32_t* d2 = (uint32_t*)(g_Q2 + ((size_t)(b * 8 + h) * S_LEN + srow0) * 64);
#pragma unroll
    for (int q = 0; q < 16; q++) {
        int linear = q * 256 + tid;
        int row = linear >> 5, c = linear & 31;
        d1[row * 32 + c] = s1[row * 33 + c];
        d2[row * 32 + c] = s2[row * 33 + c];
    }
}

// ---------------- attn_pairs: pairs + 2-plane Gram, occ 3 (R12 proven) ----
#define AP_QS1 0
#define AP_QS2 16384
#define AP_QT1 32768
#define AP_QT2 49152
#define AP_CUI  65536
#define AP_CUJ  66560
#define AP_STGD 0
#define AP_STGN 4096
#define AP_SMEM 67584

__global__ __launch_bounds__(256, 3) void attn_pairs() {
    extern __shared__ char sm[];
    uint32_t sb = smem_u32(sm);
    int tid = threadIdx.x;
    int lane = tid & 31, w = tid >> 5;
    int bid = blockIdx.x;
    int bh = bid / 136;
    int p = bid - bh * 136;
    int i = 0;
    while (p >= 16 - i) { p -= 16 - i; i++; }
    int j = i + p;
    int bhS = bh * S_LEN;

    const __nv_bfloat16* q1B = g_Q1 + (size_t)bhS * 64;
    const __nv_bfloat16* q2B = g_Q2 + (size_t)bhS * 64;
    const uint4* s1g = (const uint4*)(q1B + (size_t)(i * 128) * 64);
    const uint4* s2g = (const uint4*)(q2B + (size_t)(i * 128) * 64);
    const uint4* t1g = (const uint4*)(q1B + (size_t)(j * 128) * 64);
    const uint4* t2g = (const uint4*)(q2B + (size_t)(j * 128) * 64);

#pragma unroll
    for (int q = 0; q < 4; q++) {
        uint32_t idx = (uint32_t)(q * 256 + tid);
        uint32_t so = SW128(idx * 16);
        cp16(sb + AP_QS1 + so, s1g + idx);
        cp16(sb + AP_QS2 + so, s2g + idx);
        cp16(sb + AP_QT1 + so, t1g + idx);
        cp16(sb + AP_QT2 + so, t2g + idx);
    }
    if (tid < 64) {
        cp16(sb + AP_CUI + tid * 16, (const char*)(g_cu + bhS + i * 128) + tid * 16);
        cp16(sb + AP_CUJ + tid * 16, (const char*)(g_cu + bhS + j * 128) + tid * 16);
    }
    cp_commit();
    cp_wait<0>();
    __syncthreads();

    int row_a = w * 16 + (lane & 15);
    uint32_t a_sw = (uint32_t)((row_a & 7) << 4);
    uint32_t a_hi16 = (uint32_t)((lane >> 4) * 16);
    int nrow_base = (lane & 7) + ((lane >> 4) << 3);
    uint32_t b_sw = (uint32_t)((lane & 7) << 4);
    uint32_t b_c16 = (uint32_t)(((lane >> 3) & 1) * 16);

    uint32_t a1[4][4], a2[4][4];
    uint32_t aB1 = sb + AP_QS1 + (uint32_t)row_a * 128;
    uint32_t aB2 = sb + AP_QS2 + (uint32_t)row_a * 128;
#pragma unroll
    for (int kk = 0; kk < 4; kk++) {
        uint32_t acol = ((uint32_t)(kk * 32) + a_hi16) ^ a_sw;
        ldsm4(a1[kk], aB1 + acol);
        ldsm4(a2[kk], aB2 + acol);
    }
    __syncthreads();   // all warps done reading QS before stg aliasing writes

    const float C1 = 0.25f * LOG2E;
    const float CA = C1 * (15.0f / 16.0f);
    const float CB = C1 * (1.0f / 16.0f);
    const float2* scuI = (const float2*)(sm + AP_CUI);
    const float2* scuJ = (const float2*)(sm + AP_CUJ);
    float* stgD = (float*)(sm + AP_STGD);
    float* stgN = (float*)(sm + AP_STGN);
    int rA = w * 16 + (lane >> 2);
    float2 cuRA = scuI[rA];
    float2 cuRB = scuI[rA + 8];
    float cnA = cuRA.x, uAr = cuRA.y;
    float cnB = cuRB.x, uBr = cuRB.y;

    float den0 = 0.f, num0 = 0.f, den1 = 0.f, num1 = 0.f;
    bool offdiag = (i != j);

#pragma unroll
    for (int nb2 = 0; nb2 < 8; nb2++) {
        uint32_t nrow = (uint32_t)(nrow_base + nb2 * 16);
        float c1[2][4], c2[2][4];
#pragma unroll
        for (int nblk = 0; nblk < 2; nblk++)
#pragma unroll
            for (int r = 0; r < 4; r++) { c1[nblk][r] = 0.f; c2[nblk][r] = 0.f; }

#pragma unroll
        for (int kk = 0; kk < 4; kk++) {
            uint32_t boff = nrow * 128 + (((uint32_t)(kk * 32) + b_c16) ^ b_sw);
            uint32_t b1[4], b2[4];
            ldsm4(b1, sb + AP_QT1 + boff);
            ldsm4(b2, sb + AP_QT2 + boff);
            mma16816(c1[0], a1[kk], b1);
            mma16816(c1[1], a1[kk], b1 + 2);
            mma16816(c2[0], a2[kk], b2);
            mma16816(c2[1], a2[kk], b2 + 2);
        }

#pragma unroll
        for (int nblk = 0; nblk < 2; nblk++) {
            int nb = 2 * nb2 + nblk;
            int col0 = nb * 8 + (lane & 3) * 2;
            float2 cj0 = scuJ[col0];
            float2 cj1 = scuJ[col0 + 1];
            float w0 = ex2(fmaf(c1[nblk][0], CA, fmaf(c2[nblk][0], CB, cnA + cj0.x)));
            float w1 = ex2(fmaf(c1[nblk][1], CA, fmaf(c2[nblk][1], CB, cnA + cj1.x)));
            float w2 = ex2(fmaf(c1[nblk][2], CA, fmaf(c2[nblk][2], CB, cnB + cj0.x)));
            float w3 = ex2(fmaf(c1[nblk][3], CA, fmaf(c2[nblk][3], CB, cnB + cj1.x)));
            den0 += w0 + w1;
            num0 = fmaf(w0, cj0.y, fmaf(w1, cj1.y, num0));
            den1 += w2 + w3;
            num1 = fmaf(w2, cj0.y, fmaf(w3, cj1.y, num1));
            if (offdiag) {
                float pd0 = w0 + w2, pd1 = w1 + w3;
                float pn0 = fmaf(w0, uAr, w2 * uBr);
                float pn1 = fmaf(w1, uAr, w3 * uBr);
#pragma unroll
                for (int o = 4; o <= 16; o <<= 1) {
                    pd0 += __shfl_xor_sync(0xffffffffu, pd0, o);
                    pd1 += __shfl_xor_sync(0xffffffffu, pd1, o);
                    pn0 += __shfl_xor_sync(0xffffffffu, pn0, o);
                    pn1 += __shfl_xor_sync(0xffffffffu, pn1, o);
                }
                if (lane < 4) {
                    stgD[w * 128 + col0] = pd0;
                    stgD[w * 128 + col0 + 1] = pd1;
                    stgN[w * 128 + col0] = pn0;
                    stgN[w * 128 + col0 + 1] = pn1;
                }
            }
        }
    }

#pragma unroll
    for (int o = 1; o <= 2; o <<= 1) {
        den0 += __shfl_xor_sync(0xffffffffu, den0, o);
        num0 += __shfl_xor_sync(0xffffffffu, num0, o);
        den1 += __shfl_xor_sync(0xffffffffu, den1, o);
        num1 += __shfl_xor_sync(0xffffffffu, num1, o);
    }
    if ((lane & 3) == 0) {
        size_t gr = ((size_t)bhS + i * 128 + rA) * 16 + j;
        g_pd[gr] = den0;
        g_pn[gr] = num0;
        g_pd[gr + 8 * 16] = den1;
        g_pn[gr + 8 * 16] = num1;
    }

    if (offdiag) {
        __syncthreads();
        if (tid < 128) {
            float d = 0.f, n = 0.f;
#pragma unroll
            for (int ww = 0; ww < 8; ww++) {
                d += stgD[ww * 128 + tid];
                n += stgN[ww * 128 + tid];
            }
            size_t gr = ((size_t)bhS + j * 128 + tid) * 16 + i;
            g_pd[gr] = d;
            g_pn[gr] = n;
        }
    }
}

// ---------------- attn_final ----------------
__global__ __launch_bounds__(256) void attn_final(float* __restrict__ out) {
    int r = blockIdx.x * 256 + threadIdx.x;   // 0..32767
    const float4* pd = (const float4*)(g_pd + (size_t)r * 16);
    const float4* pn = (const float4*)(g_pn + (size_t)r * 16);
    float d = 0.f, n = 0.f;
#pragma unroll
    for (int q = 0; q < 4; q++) {
        float4 vd = pd[q], vn = pn[q];
        d += (vd.x + vd.y) + (vd.z + vd.w);
        n += (vn.x + vn.y) + (vn.z + vn.w);
    }
    float z = n / d;
    out[r] = 1.0f / (1.0f + ex2(-z * LOG2E));
}

// ---------------- launch ----------------
extern "C" void kernel_launch(void* const* d_in, const int* in_sizes, int n_in,
                              void* d_out, int out_size) {
    const float *X = nullptr, *Wq = nullptr, *Wv = nullptr;
    for (int i = 0; i < n_in; i++) {
        if (in_sizes[i] == 2 * 2048 * 512)      X  = (const float*)d_in[i];
        else if (in_sizes[i] == 512 * 512)      Wq = (const float*)d_in[i];
        else if (in_sizes[i] == 512)            Wv = (const float*)d_in[i];
    }
    float* out = (float*)d_out;

    cudaFuncSetAttribute(gemm_q, cudaFuncAttributeMaxDynamicSharedMemorySize, GQ_SMEM);
    cudaFuncSetAttribute(attn_pairs, cudaFuncAttributeMaxDynamicSharedMemorySize, AP_SMEM);

    convert_w<<<256, 256>>>(Wq);
    calc_g<<<64, 256>>>(Wv);
    convert_x<<<1024, 256>>>(X);
    gemm_q<<<256, 256, GQ_SMEM>>>();
    attn_pairs<<<NBH * 136, 256, AP_SMEM>>>();
    attn_final<<<128, 256>>>(out);
}

// round 16
// speedup vs baseline: 1.1135x; 1.1135x over previous
#include <cuda_runtime.h>
#include <cuda_bf16.h>
#include <cstdint>

#define S_LEN 2048
#define D_DIM 512
#define NH 8
#define NROWS 4096   // B*S
#define NBH 16       // B*H

// ---------------- scratch (static device globals; no allocs) ----------------
__device__ float g_g[D_DIM];
__device__ float2 g_cu[NBH * S_LEN];                               // {cn, u}
__device__ __align__(128) __nv_bfloat16 g_Q1[NBH * S_LEN * 64];    // plane1 = bf16(Q)
__device__ __align__(128) __nv_bfloat16 g_Q2[NBH * S_LEN * 64];    // plane2 = bf16(hi+16*lo)
__device__ __align__(128) __nv_bfloat16 g_X1[NROWS * D_DIM];       // plane1 = bf16(x)
__device__ __align__(128) __nv_bfloat16 g_X2[NROWS * D_DIM];       // plane2 = bf16(xh+16xl)/4
__device__ __align__(128) __nv_bfloat16 g_W1[D_DIM * D_DIM];       // [n][k] plane1 = bf16(w)
__device__ __align__(128) __nv_bfloat16 g_W2[D_DIM * D_DIM];       // [n][k] plane2 (/4)
__device__ __align__(128) float g_Wt[D_DIM * D_DIM];               // [n][k] fp32
__device__ __align__(128) float g_pd[NBH * S_LEN * 16];            // den partials
__device__ __align__(128) float g_pn[NBH * S_LEN * 16];            // num partials

// ---------------- helpers ----------------
__device__ __forceinline__ float ex2(float x) {
    float r; asm("ex2.approx.ftz.f32 %0, %1;" : "=f"(r) : "f"(x)); return r;
}
__device__ __forceinline__ uint32_t smem_u32(const void* p) {
    uint32_t a;
    asm("{ .reg .u64 t; cvta.to.shared.u64 t, %1; cvt.u32.u64 %0, t; }" : "=r"(a) : "l"(p));
    return a;
}
#define LOG2E 1.4426950408889634f
#define SW128(o) ((o) ^ ((((uint32_t)(o)) >> 3) & 0x70))

__device__ __forceinline__ void ldsm4(uint32_t* r, uint32_t addr) {
    asm volatile("ldmatrix.sync.aligned.m8n8.x4.shared.b16 {%0,%1,%2,%3}, [%4];"
                 : "=r"(r[0]), "=r"(r[1]), "=r"(r[2]), "=r"(r[3]) : "r"(addr));
}
__device__ __forceinline__ void mma16816(float* c, const uint32_t* a, const uint32_t* b) {
    asm volatile("mma.sync.aligned.m16n8k16.row.col.f32.bf16.bf16.f32 "
                 "{%0,%1,%2,%3}, {%4,%5,%6,%7}, {%8,%9}, {%0,%1,%2,%3};"
                 : "+f"(c[0]), "+f"(c[1]), "+f"(c[2]), "+f"(c[3])
                 : "r"(a[0]), "r"(a[1]), "r"(a[2]), "r"(a[3]), "r"(b[0]), "r"(b[1]));
}
__device__ __forceinline__ void cp16(uint32_t dst, const void* src) {
    asm volatile("cp.async.cg.shared.global [%0], [%1], 16;" :: "r"(dst), "l"(src));
}
__device__ __forceinline__ void cp_commit() {
    asm volatile("cp.async.commit_group;" ::: "memory");
}
template <int N>
__device__ __forceinline__ void cp_wait() {
    asm volatile("cp.async.wait_group %0;" :: "n"(N) : "memory");
}
// general-product two-plane split: plane1 = bf16(v), plane2 = bf16(h+16*l) * 0.25 (exact)
__device__ __forceinline__ uint32_t packgp(float a, float b, uint32_t& p2) {
    __nv_bfloat16 h0 = __float2bfloat16(a);
    __nv_bfloat16 h1 = __float2bfloat16(b);
    float f0 = __bfloat162float(h0), f1 = __bfloat162float(h1);
    __nv_bfloat162 hh; hh.x = h0; hh.y = h1;
    __nv_bfloat162 pp;
    pp.x = __float2bfloat16(fmaf(16.f, a - f0, f0) * 0.25f);
    pp.y = __float2bfloat16(fmaf(16.f, b - f1, f1) * 0.25f);
    p2 = *(uint32_t*)&pp;
    return *(uint32_t*)&hh;
}
// symmetric Gram two-plane split: plane1 = bf16(q), plane2 = bf16(h + 16*l)
__device__ __forceinline__ uint32_t packp(float a, float b, uint32_t& p2) {
    __nv_bfloat16 h0 = __float2bfloat16(a);
    __nv_bfloat16 h1 = __float2bfloat16(b);
    float f0 = __bfloat162float(h0), f1 = __bfloat162float(h1);
    __nv_bfloat162 hh; hh.x = h0; hh.y = h1;
    __nv_bfloat162 pp;
    pp.x = __float2bfloat16(fmaf(16.f, a - f0, f0));
    pp.y = __float2bfloat16(fmaf(16.f, b - f1, f1));
    p2 = *(uint32_t*)&pp;
    return *(uint32_t*)&hh;
}

// ---------------- merged convert: blocks 0..255 = W, 256..1279 = X --------
__global__ __launch_bounds__(256) void convert_wx(const float* __restrict__ W,
                                                  const float* __restrict__ X) {
    if (blockIdx.x < 256) {
        __shared__ float tile[32][33];
        int bid = blockIdx.x;
        int k0 = (bid & 15) * 32;
        int n0 = (bid >> 4) * 32;
        int tid = threadIdx.x;
        int r = tid >> 5, c = tid & 31;
#pragma unroll
        for (int p = 0; p < 4; p++)
            tile[p * 8 + r][c] = W[(size_t)(k0 + p * 8 + r) * 512 + n0 + c];
        __syncthreads();
#pragma unroll
        for (int p = 0; p < 4; p++) {
            int nr = p * 8 + r;
            float v = tile[c][nr];
            size_t o = (size_t)(n0 + nr) * 512 + k0 + c;
            g_Wt[o] = v;
            __nv_bfloat16 h = __float2bfloat16(v);
            float fh = __bfloat162float(h);
            g_W1[o] = h;
            g_W2[o] = __float2bfloat16(fmaf(16.f, v - fh, fh) * 0.25f);
        }
    } else {
        int gid = (blockIdx.x - 256) * 256 + threadIdx.x;
        const float4* src = (const float4*)X;
        uint2* d1 = (uint2*)g_X1;
        uint2* d2 = (uint2*)g_X2;
#pragma unroll
        for (int r = 0; r < 2; r++) {
            int i = gid * 2 + r;
            float4 v = src[i];
            uint2 p1, p2;
            p1.x = packgp(v.x, v.y, p2.x);
            p1.y = packgp(v.z, v.w, p2.y);
            d1[i] = p1;
            d2[i] = p2;
        }
    }
}

// ---------------- calc_g ----------------
__global__ __launch_bounds__(256) void calc_g(const float* __restrict__ Wv) {
    int warp = blockIdx.x * 8 + (threadIdx.x >> 5);   // 512
    int lane = threadIdx.x & 31;
    const float* wt = g_Wt + (size_t)warp * 512;
    float a = 0.f;
#pragma unroll
    for (int m = 0; m < 16; m++) {
        int k = lane + 32 * m;
        a = fmaf(wt[k], Wv[k], a);
    }
#pragma unroll
    for (int o = 16; o > 0; o >>= 1) a += __shfl_xor_sync(0xffffffffu, a, o);
    if (lane == 0) g_g[warp] = a;
}

// ---------------- gemm_q: Q = (15/16)A1W1 + A2W2 (two banks, R14 proven) --
#define GQ_STAGE 49152
#define GQ_A1 0
#define GQ_A2 16384
#define GQ_B1 32768
#define GQ_B2 40960
#define GQ_SMEM (2 * GQ_STAGE)

__device__ __forceinline__ void gq_load(uint32_t base,
        const __nv_bfloat16* A1, const __nv_bfloat16* A2,
        const __nv_bfloat16* B1, const __nv_bfloat16* B2,
        int kc, int tid) {
#pragma unroll
    for (int q = 0; q < 4; q++) {
        int idx = q * 256 + tid;
        int row = idx >> 3, cg = idx & 7;
        uint32_t so = SW128((uint32_t)idx * 16);
        cp16(base + GQ_A1 + so, A1 + (size_t)row * 512 + kc + cg * 8);
        cp16(base + GQ_A2 + so, A2 + (size_t)row * 512 + kc + cg * 8);
    }
#pragma unroll
    for (int q = 0; q < 2; q++) {
        int idx = q * 256 + tid;
        int row = idx >> 3, cg = idx & 7;
        uint32_t so = SW128((uint32_t)idx * 16);
        cp16(base + GQ_B1 + so, B1 + (size_t)row * 512 + kc + cg * 8);
        cp16(base + GQ_B2 + so, B2 + (size_t)row * 512 + kc + cg * 8);
    }
}

__global__ __launch_bounds__(256, 2) void gemm_q() {
    extern __shared__ char sm[];
    uint32_t sb = smem_u32(sm);
    int tid = threadIdx.x, lane = tid & 31, w = tid >> 5;
    int bid = blockIdx.x;
    int r0 = (bid >> 3) * 128;
    int h = bid & 7;
    int b = r0 >> 11, srow0 = r0 & 2047;
    const __nv_bfloat16* A1 = g_X1 + (size_t)r0 * 512;
    const __nv_bfloat16* A2 = g_X2 + (size_t)r0 * 512;
    const __nv_bfloat16* B1 = g_W1 + (size_t)h * 64 * 512;
    const __nv_bfloat16* B2 = g_W2 + (size_t)h * 64 * 512;

    int row_a = w * 16 + (lane & 15);
    uint32_t a_sw = (uint32_t)((row_a & 7) << 4);
    uint32_t a_hi16 = (uint32_t)((lane >> 4) * 16);
    int nrow_base = (lane & 7) + ((lane >> 4) << 3);
    uint32_t b_sw = (uint32_t)((lane & 7) << 4);
    uint32_t b_c16 = (uint32_t)(((lane >> 3) & 1) * 16);

    float c1a[8][4], c2a[8][4];
#pragma unroll
    for (int nb = 0; nb < 8; nb++)
#pragma unroll
        for (int r = 0; r < 4; r++) { c1a[nb][r] = 0.f; c2a[nb][r] = 0.f; }

    gq_load(sb, A1, A2, B1, B2, 0, tid);
    cp_commit();

    for (int i = 0; i < 8; i++) {
        int buf = i & 1;
        __syncthreads();
        if (i < 7) {
            gq_load(sb + (buf ^ 1) * GQ_STAGE, A1, A2, B1, B2, (i + 1) * 64, tid);
            cp_commit();
            cp_wait<1>();
        } else {
            cp_wait<0>();
        }
        __syncthreads();
        uint32_t aB1 = sb + buf * GQ_STAGE + GQ_A1 + (uint32_t)row_a * 128;
        uint32_t aB2 = sb + buf * GQ_STAGE + GQ_A2 + (uint32_t)row_a * 128;
        uint32_t bB1 = sb + buf * GQ_STAGE + GQ_B1;
        uint32_t bB2 = sb + buf * GQ_STAGE + GQ_B2;
#pragma unroll
        for (int kk = 0; kk < 4; kk++) {
            uint32_t acol = ((uint32_t)(kk * 32) + a_hi16) ^ a_sw;
            uint32_t a1[4], a2[4];
            ldsm4(a1, aB1 + acol);
            ldsm4(a2, aB2 + acol);
            uint32_t bcol = ((uint32_t)(kk * 32) + b_c16) ^ b_sw;
#pragma unroll
            for (int nb2 = 0; nb2 < 4; nb2++) {
                uint32_t boff = (uint32_t)(nrow_base + nb2 * 16) * 128 + bcol;
                uint32_t b1[4], b2[4];
                ldsm4(b1, bB1 + boff);
                ldsm4(b2, bB2 + boff);
                mma16816(c1a[2 * nb2],     a1, b1);
                mma16816(c1a[2 * nb2 + 1], a1, b1 + 2);
                mma16816(c2a[2 * nb2],     a2, b2);
                mma16816(c2a[2 * nb2 + 1], a2, b2 + 2);
            }
        }
    }
    __syncthreads();

    // ---- combine banks: Q = (15/16) c1 + c2 ----
    float cacc[8][4];
#pragma unroll
    for (int nb = 0; nb < 8; nb++)
#pragma unroll
        for (int r = 0; r < 4; r++)
            cacc[nb][r] = fmaf(c1a[nb][r], 0.9375f, c2a[nb][r]);

    // ---- norms + u = Q.g ----
    float sA = 0.f, sB = 0.f, uA = 0.f, uB = 0.f;
#pragma unroll
    for (int nb = 0; nb < 8; nb++) {
        int c0 = nb * 8 + (lane & 3) * 2;
        float2 gg = *(const float2*)&g_g[h * 64 + c0];
        sA = fmaf(cacc[nb][0], cacc[nb][0], sA);
        sA = fmaf(cacc[nb][1], cacc[nb][1], sA);
        sB = fmaf(cacc[nb][2], cacc[nb][2], sB);
        sB = fmaf(cacc[nb][3], cacc[nb][3], sB);
        uA = fmaf(cacc[nb][0], gg.x, uA);
        uA = fmaf(cacc[nb][1], gg.y, uA);
        uB = fmaf(cacc[nb][2], gg.x, uB);
        uB = fmaf(cacc[nb][3], gg.y, uB);
    }
#pragma unroll
    for (int o = 1; o <= 2; o <<= 1) {
        sA += __shfl_xor_sync(0xffffffffu, sA, o);
        sB += __shfl_xor_sync(0xffffffffu, sB, o);
        uA += __shfl_xor_sync(0xffffffffu, uA, o);
        uB += __shfl_xor_sync(0xffffffffu, uB, o);
    }
    int rA = w * 16 + (lane >> 2);
    if ((lane & 3) == 0) {
        int base = (b * 8 + h) * S_LEN + srow0;
        g_cu[base + rA]     = make_float2(-0.125f * LOG2E * sqrtf(sA), uA);
        g_cu[base + rA + 8] = make_float2(-0.125f * LOG2E * sqrtf(sB), uB);
    }

    // ---- stage Q planes (padded [128][33] u32) ----
    uint32_t* s1 = (uint32_t*)sm;
    uint32_t* s2 = (uint32_t*)(sm + 16896);
#pragma unroll
    for (int nb = 0; nb < 8; nb++) {
        int cslot = nb * 4 + (lane & 3);
        uint32_t p0, p1;
        uint32_t h0 = packp(cacc[nb][0], cacc[nb][1], p0);
        uint32_t h1 = packp(cacc[nb][2], cacc[nb][3], p1);
        s1[rA * 33 + cslot] = h0;
        s2[rA * 33 + cslot] = p0;
        s1[(rA + 8) * 33 + cslot] = h1;
        s2[(rA + 8) * 33 + cslot] = p1;
    }
    __syncthreads();
    uint32_t* d1 = (uint32_t*)(g_Q1 + ((size_t)(b * 8 + h) * S_LEN + srow0) * 64);
    uint32_t* d2 = (uint32_t*)(g_Q2 + ((size_t)(b * 8 + h) * S_LEN + srow0) * 64);
#pragma unroll
    for (int q = 0; q < 16; q++) {
        int linear = q * 256 + tid;
        int row = linear >> 5, c = linear & 31;
        d1[row * 32 + c] = s1[row * 33 + c];
        d2[row * 32 + c] = s2[row * 33 + c];
    }
}

// ---------------- attn_pairs: occ 3, 2-level col shfl + 2-partial stg -----
// smem: QS1 16K | QS2 16K | QT1 16K | QT2 16K | CUI 1K | CUJ 1K = 67584 B
// stg: D 8K @0, N 8K @8192 — alias QS1 (dead after A-frag register load).
#define AP_QS1 0
#define AP_QS2 16384
#define AP_QT1 32768
#define AP_QT2 49152
#define AP_CUI  65536
#define AP_CUJ  66560
#define AP_STGD 0
#define AP_STGN 8192
#define AP_SMEM 67584

__global__ __launch_bounds__(256, 3) void attn_pairs() {
    extern __shared__ char sm[];
    uint32_t sb = smem_u32(sm);
    int tid = threadIdx.x;
    int lane = tid & 31, w = tid >> 5;
    int bid = blockIdx.x;
    int bh = bid / 136;
    int p = bid - bh * 136;
    int i = 0;
    while (p >= 16 - i) { p -= 16 - i; i++; }
    int j = i + p;
    int bhS = bh * S_LEN;

    const __nv_bfloat16* q1B = g_Q1 + (size_t)bhS * 64;
    const __nv_bfloat16* q2B = g_Q2 + (size_t)bhS * 64;
    const uint4* s1g = (const uint4*)(q1B + (size_t)(i * 128) * 64);
    const uint4* s2g = (const uint4*)(q2B + (size_t)(i * 128) * 64);
    const uint4* t1g = (const uint4*)(q1B + (size_t)(j * 128) * 64);
    const uint4* t2g = (const uint4*)(q2B + (size_t)(j * 128) * 64);

#pragma unroll
    for (int q = 0; q < 4; q++) {
        uint32_t idx = (uint32_t)(q * 256 + tid);
        uint32_t so = SW128(idx * 16);
        cp16(sb + AP_QS1 + so, s1g + idx);
        cp16(sb + AP_QS2 + so, s2g + idx);
        cp16(sb + AP_QT1 + so, t1g + idx);
        cp16(sb + AP_QT2 + so, t2g + idx);
    }
    if (tid < 64) {
        cp16(sb + AP_CUI + tid * 16, (const char*)(g_cu + bhS + i * 128) + tid * 16);
        cp16(sb + AP_CUJ + tid * 16, (const char*)(g_cu + bhS + j * 128) + tid * 16);
    }
    cp_commit();
    cp_wait<0>();
    __syncthreads();

    int row_a = w * 16 + (lane & 15);
    uint32_t a_sw = (uint32_t)((row_a & 7) << 4);
    uint32_t a_hi16 = (uint32_t)((lane >> 4) * 16);
    int nrow_base = (lane & 7) + ((lane >> 4) << 3);
    uint32_t b_sw = (uint32_t)((lane & 7) << 4);
    uint32_t b_c16 = (uint32_t)(((lane >> 3) & 1) * 16);

    uint32_t a1[4][4], a2[4][4];
    uint32_t aB1 = sb + AP_QS1 + (uint32_t)row_a * 128;
    uint32_t aB2 = sb + AP_QS2 + (uint32_t)row_a * 128;
#pragma unroll
    for (int kk = 0; kk < 4; kk++) {
        uint32_t acol = ((uint32_t)(kk * 32) + a_hi16) ^ a_sw;
        ldsm4(a1[kk], aB1 + acol);
        ldsm4(a2[kk], aB2 + acol);
    }
    __syncthreads();   // all warps done reading QS before stg aliasing writes

    const float C1 = 0.25f * LOG2E;
    const float CA = C1 * (15.0f / 16.0f);
    const float CB = C1 * (1.0f / 16.0f);
    const float2* scuI = (const float2*)(sm + AP_CUI);
    const float2* scuJ = (const float2*)(sm + AP_CUJ);
    float* stgD = (float*)(sm + AP_STGD);   // [8 warps][2 halves][128 cols]
    float* stgN = (float*)(sm + AP_STGN);
    int rA = w * 16 + (lane >> 2);
    float2 cuRA = scuI[rA];
    float2 cuRB = scuI[rA + 8];
    float cnA = cuRA.x, uAr = cuRA.y;
    float cnB = cuRB.x, uBr = cuRB.y;

    float den0 = 0.f, num0 = 0.f, den1 = 0.f, num1 = 0.f;
    bool offdiag = (i != j);
    int half = lane >> 4;
    bool stg_lane = ((lane & 12) == 0);

#pragma unroll
    for (int nb2 = 0; nb2 < 8; nb2++) {
        uint32_t nrow = (uint32_t)(nrow_base + nb2 * 16);
        float c1[2][4], c2[2][4];
#pragma unroll
        for (int nblk = 0; nblk < 2; nblk++)
#pragma unroll
            for (int r = 0; r < 4; r++) { c1[nblk][r] = 0.f; c2[nblk][r] = 0.f; }

#pragma unroll
        for (int kk = 0; kk < 4; kk++) {
            uint32_t boff = nrow * 128 + (((uint32_t)(kk * 32) + b_c16) ^ b_sw);
            uint32_t b1[4], b2[4];
            ldsm4(b1, sb + AP_QT1 + boff);
            ldsm4(b2, sb + AP_QT2 + boff);
            mma16816(c1[0], a1[kk], b1);
            mma16816(c1[1], a1[kk], b1 + 2);
            mma16816(c2[0], a2[kk], b2);
            mma16816(c2[1], a2[kk], b2 + 2);
        }

#pragma unroll
        for (int nblk = 0; nblk < 2; nblk++) {
            int nb = 2 * nb2 + nblk;
            int col0 = nb * 8 + (lane & 3) * 2;
            float2 cj0 = scuJ[col0];
            float2 cj1 = scuJ[col0 + 1];
            float w0 = ex2(fmaf(c1[nblk][0], CA, fmaf(c2[nblk][0], CB, cnA + cj0.x)));
            float w1 = ex2(fmaf(c1[nblk][1], CA, fmaf(c2[nblk][1], CB, cnA + cj1.x)));
            float w2 = ex2(fmaf(c1[nblk][2], CA, fmaf(c2[nblk][2], CB, cnB + cj0.x)));
            float w3 = ex2(fmaf(c1[nblk][3], CA, fmaf(c2[nblk][3], CB, cnB + cj1.x)));
            den0 += w0 + w1;
            num0 = fmaf(w0, cj0.y, fmaf(w1, cj1.y, num0));
            den1 += w2 + w3;
            num1 = fmaf(w2, cj0.y, fmaf(w3, cj1.y, num1));
            if (offdiag) {
                float pd0 = w0 + w2, pd1 = w1 + w3;
                float pn0 = fmaf(w0, uAr, w2 * uBr);
                float pn1 = fmaf(w1, uAr, w3 * uBr);
                // reduce over lane bits 2,3 only (keep bit4 as 2nd partial)
#pragma unroll
                for (int o = 4; o <= 8; o <<= 1) {
                    pd0 += __shfl_xor_sync(0xffffffffu, pd0, o);
                    pd1 += __shfl_xor_sync(0xffffffffu, pd1, o);
                    pn0 += __shfl_xor_sync(0xffffffffu, pn0, o);
                    pn1 += __shfl_xor_sync(0xffffffffu, pn1, o);
                }
                if (stg_lane) {
                    int sidx = w * 256 + half * 128 + col0;
                    stgD[sidx] = pd0;
                    stgD[sidx + 1] = pd1;
                    stgN[sidx] = pn0;
                    stgN[sidx + 1] = pn1;
                }
            }
        }
    }

    // row-side reduce & write (slot j for rows of block i)
#pragma unroll
    for (int o = 1; o <= 2; o <<= 1) {
        den0 += __shfl_xor_sync(0xffffffffu, den0, o);
        num0 += __shfl_xor_sync(0xffffffffu, num0, o);
        den1 += __shfl_xor_sync(0xffffffffu, den1, o);
        num1 += __shfl_xor_sync(0xffffffffu, num1, o);
    }
    if ((lane & 3) == 0) {
        size_t gr = ((size_t)bhS + i * 128 + rA) * 16 + j;
        g_pd[gr] = den0;
        g_pn[gr] = num0;
        g_pd[gr + 8 * 16] = den1;
        g_pn[gr + 8 * 16] = num1;
    }

    // col-side reduce & write (slot i for rows of block j)
    if (offdiag) {
        __syncthreads();
        if (tid < 128) {
            float d = 0.f, n = 0.f;
#pragma unroll
            for (int s = 0; s < 16; s++) {
                d += stgD[s * 128 + tid];
                n += stgN[s * 128 + tid];
            }
            size_t gr = ((size_t)bhS + j * 128 + tid) * 16 + i;
            g_pd[gr] = d;
            g_pn[gr] = n;
        }
    }
}

// ---------------- attn_final ----------------
__global__ __launch_bounds__(256) void attn_final(float* __restrict__ out) {
    int r = blockIdx.x * 256 + threadIdx.x;   // 0..32767
    const float4* pd = (const float4*)(g_pd + (size_t)r * 16);
    const float4* pn = (const float4*)(g_pn + (size_t)r * 16);
    float d = 0.f, n = 0.f;
#pragma unroll
    for (int q = 0; q < 4; q++) {
        float4 vd = pd[q], vn = pn[q];
        d += (vd.x + vd.y) + (vd.z + vd.w);
        n += (vn.x + vn.y) + (vn.z + vn.w);
    }
    float z = n / d;
    out[r] = 1.0f / (1.0f + ex2(-z * LOG2E));
}

// ---------------- launch ----------------
extern "C" void kernel_launch(void* const* d_in, const int* in_sizes, int n_in,
                              void* d_out, int out_size) {
    const float *X = nullptr, *Wq = nullptr, *Wv = nullptr;
    for (int i = 0; i < n_in; i++) {
        if (in_sizes[i] == 2 * 2048 * 512)      X  = (const float*)d_in[i];
        else if (in_sizes[i] == 512 * 512)      Wq = (const float*)d_in[i];
        else if (in_sizes[i] == 512)            Wv = (const float*)d_in[i];
    }
    float* out = (float*)d_out;

    cudaFuncSetAttribute(gemm_q, cudaFuncAttributeMaxDynamicSharedMemorySize, GQ_SMEM);
    cudaFuncSetAttribute(attn_pairs, cudaFuncAttributeMaxDynamicSharedMemorySize, AP_SMEM);

    convert_wx<<<1280, 256>>>(Wq, X);
    calc_g<<<64, 256>>>(Wv);
    gemm_q<<<256, 256, GQ_SMEM>>>();
    attn_pairs<<<NBH * 136, 256, AP_SMEM>>>();
    attn_final<<<128, 256>>>(out);
}